// round 12
// baseline (speedup 1.0000x reference)
#include <cuda_runtime.h>
#include <cstdint>

#define NN    50000
#define NE    600000
#define TE    (NE + NN)
#define HD    128
#define BB    128
#define KSEL  30
#define COUT  32
#define KERW  5
#define LOUT  26
#define ODIM  10
#define PSTR  129
#define DSLOT 64      // fixed per-node edge slots (Poisson(13) -> max deg << 64)

// pipeline chunking: 4 chunks, starts aligned to 128 (gemm tile) and 8 (agg block)
#define NCHUNK 4
static const int CH_START[NCHUNK + 1] = {0, 12544, 25088, 37632, 50000};

// ---------------- device scratch ----------------
static __device__ int   g_cur[NN];
static __device__ float g_dinv[NN];
static __device__ __align__(16) int g_srcv[NN * DSLOT];
static __device__ float g_hw1[NN * HD];   // gemm output, layers 1 & 3
static __device__ float g_hw2[NN * HD];   // gemm output, layer 2
static __device__ float g_hA[NN * HD];
static __device__ float g_hB[NN * HD];

// ---------------- f32x2 packed helpers ----------------
__device__ __forceinline__ unsigned long long pk2(float a, float b) {
    unsigned long long r;
    asm("mov.b64 %0, {%1, %2};" : "=l"(r) : "f"(a), "f"(b));
    return r;
}
__device__ __forceinline__ void fma2(unsigned long long& d, unsigned long long a, unsigned long long b) {
    asm("fma.rn.f32x2 %0, %1, %2, %0;" : "+l"(d) : "l"(a), "l"(b));
}

// ---------------- graph build (bucketed, no scan) ----------------
__global__ void k_init() {
    int i = blockIdx.x * 256 + threadIdx.x;
    if (i < NN) g_cur[i] = 0;
}

__global__ void k_fill(const int* __restrict__ ei) {
    int e = blockIdx.x * 256 + threadIdx.x;
    if (e >= TE) return;
    int src, dst;
    if (e < NE) { src = ei[e]; dst = ei[NE + e]; }
    else        { src = dst = e - NE; }          // self-loop
    int pos = atomicAdd(&g_cur[dst], 1);
    if (pos < DSLOT) g_srcv[dst * DSLOT + pos] = src;
}

__global__ void k_dinv() {
    int i = blockIdx.x * 256 + threadIdx.x;
    if (i < NN) g_dinv[i] = rsqrtf((float)g_cur[i]);
}

// ---------------- GEMM: hw_out(rows roff..) = A @ W, round-7 proven version ------
__global__ __launch_bounds__(256, 2) void k_gemm(const float* __restrict__ A,
                                                 const float* __restrict__ W,
                                                 float* __restrict__ hw_out,
                                                 int roff) {
    __shared__ float Ash[2][16][132];
    __shared__ float Bsh[2][16][128];
    const int tid = threadIdx.x;
    const int m0 = roff + blockIdx.x * 128;
    const int ty = tid >> 4;
    const int tx = tid & 15;

    unsigned long long acc[8][4];
    #pragma unroll
    for (int i = 0; i < 8; i++)
        #pragma unroll
        for (int j = 0; j < 4; j++) acc[i][j] = 0ULL;

    float4 ra[2], rb[2];
    #pragma unroll
    for (int s = 0; s < 2; s++) {
        int idx = tid * 2 + s;
        int m = idx >> 2, q = idx & 3;
        int row = m0 + m;
        ra[s] = (row < NN) ? *reinterpret_cast<const float4*>(&A[row * HD + q * 4])
                           : make_float4(0.f, 0.f, 0.f, 0.f);
        int k = idx >> 5, n4 = (idx & 31) * 4;
        rb[s] = *reinterpret_cast<const float4*>(&W[k * HD + n4]);
    }

    #pragma unroll
    for (int kb = 0; kb < 8; kb++) {
        const int cur = kb & 1;
        #pragma unroll
        for (int s = 0; s < 2; s++) {
            int idx = tid * 2 + s;
            int m = idx >> 2, q = idx & 3;
            Ash[cur][q * 4 + 0][m] = ra[s].x; Ash[cur][q * 4 + 1][m] = ra[s].y;
            Ash[cur][q * 4 + 2][m] = ra[s].z; Ash[cur][q * 4 + 3][m] = ra[s].w;
            int k = idx >> 5, n4 = (idx & 31) * 4;
            *reinterpret_cast<float4*>(&Bsh[cur][k][n4]) = rb[s];
        }
        __syncthreads();
        if (kb < 7) {
            int k0 = (kb + 1) * 16;
            #pragma unroll
            for (int s = 0; s < 2; s++) {
                int idx = tid * 2 + s;
                int m = idx >> 2, q = idx & 3;
                int row = m0 + m;
                ra[s] = (row < NN) ? *reinterpret_cast<const float4*>(&A[row * HD + k0 + q * 4])
                                   : make_float4(0.f, 0.f, 0.f, 0.f);
                int k = idx >> 5, n4 = (idx & 31) * 4;
                rb[s] = *reinterpret_cast<const float4*>(&W[(k0 + k) * HD + n4]);
            }
        }
        #pragma unroll
        for (int k = 0; k < 16; k++) {
            float4 a0 = *reinterpret_cast<const float4*>(&Ash[cur][k][ty * 8]);
            float4 a1 = *reinterpret_cast<const float4*>(&Ash[cur][k][ty * 8 + 4]);
            float av[8] = {a0.x, a0.y, a0.z, a0.w, a1.x, a1.y, a1.z, a1.w};
            ulonglong2 b0 = *reinterpret_cast<const ulonglong2*>(&Bsh[cur][k][tx * 4]);
            ulonglong2 b1 = *reinterpret_cast<const ulonglong2*>(&Bsh[cur][k][64 + tx * 4]);
            unsigned long long bv[4] = {b0.x, b0.y, b1.x, b1.y};
            #pragma unroll
            for (int i = 0; i < 8; i++) {
                unsigned long long ad = pk2(av[i], av[i]);
                #pragma unroll
                for (int j = 0; j < 4; j++) fma2(acc[i][j], ad, bv[j]);
            }
        }
        __syncthreads();
    }
    #pragma unroll
    for (int i = 0; i < 8; i++) {
        int row = m0 + ty * 8 + i;
        if (row < NN) {
            union { unsigned long long u[2]; float4 f; } p0, p1;
            p0.u[0] = acc[i][0]; p0.u[1] = acc[i][1];
            p1.u[0] = acc[i][2]; p1.u[1] = acc[i][3];
            *reinterpret_cast<float4*>(&hw_out[row * HD + tx * 4])      = p0.f;
            *reinterpret_cast<float4*>(&hw_out[row * HD + 64 + tx * 4]) = p1.f;
        }
    }
}

// ---------------- aggregation: warp per node (round-7 proven), node-range chunk ----
template<bool GATHER_DINV, bool SCALE_OUT>
__global__ __launch_bounds__(256) void k_agg(const float* __restrict__ hw_in,
                                             const float* __restrict__ bias,
                                             float* __restrict__ hout,
                                             int noff, int nend) {
    int w = noff + ((blockIdx.x * 256 + threadIdx.x) >> 5);
    int lane = threadIdx.x & 31;
    if (w >= nend) return;
    int deg = g_cur[w]; if (deg > DSLOT) deg = DSLOT;
    const int* lst = &g_srcv[w * DSLOT];
    const float4* hw4 = reinterpret_cast<const float4*>(hw_in);
    float4 acc = make_float4(0.f, 0.f, 0.f, 0.f);

    int e = 0;
    for (; e + 8 <= deg; e += 8) {
        int s[8];
        #pragma unroll
        for (int u = 0; u < 8; u++) s[u] = __ldg(&lst[e + u]);
        float c[8];
        #pragma unroll
        for (int u = 0; u < 8; u++) c[u] = GATHER_DINV ? __ldg(&g_dinv[s[u]]) : 1.f;
        float4 v[8];
        #pragma unroll
        for (int u = 0; u < 8; u++) v[u] = __ldg(&hw4[s[u] * 32 + lane]);
        #pragma unroll
        for (int u = 0; u < 8; u++) {
            if (GATHER_DINV) {
                acc.x += c[u] * v[u].x; acc.y += c[u] * v[u].y;
                acc.z += c[u] * v[u].z; acc.w += c[u] * v[u].w;
            } else {
                acc.x += v[u].x; acc.y += v[u].y;
                acc.z += v[u].z; acc.w += v[u].w;
            }
        }
    }
    if (e + 4 <= deg) {
        int s[4];
        #pragma unroll
        for (int u = 0; u < 4; u++) s[u] = __ldg(&lst[e + u]);
        float c[4];
        #pragma unroll
        for (int u = 0; u < 4; u++) c[u] = GATHER_DINV ? __ldg(&g_dinv[s[u]]) : 1.f;
        float4 v[4];
        #pragma unroll
        for (int u = 0; u < 4; u++) v[u] = __ldg(&hw4[s[u] * 32 + lane]);
        #pragma unroll
        for (int u = 0; u < 4; u++) {
            if (GATHER_DINV) {
                acc.x += c[u] * v[u].x; acc.y += c[u] * v[u].y;
                acc.z += c[u] * v[u].z; acc.w += c[u] * v[u].w;
            } else {
                acc.x += v[u].x; acc.y += v[u].y;
                acc.z += v[u].z; acc.w += v[u].w;
            }
        }
        e += 4;
    }
    for (; e < deg; e++) {
        int s = __ldg(&lst[e]);
        float c = GATHER_DINV ? __ldg(&g_dinv[s]) : 1.f;
        float4 v = __ldg(&hw4[s * 32 + lane]);
        if (GATHER_DINV) {
            acc.x += c * v.x; acc.y += c * v.y; acc.z += c * v.z; acc.w += c * v.w;
        } else {
            acc.x += v.x; acc.y += v.y; acc.z += v.z; acc.w += v.w;
        }
    }

    float dn = g_dinv[w];
    float4 bb = reinterpret_cast<const float4*>(bias)[lane];
    float4 r;
    r.x = fmaxf(acc.x * dn + bb.x, 0.f);
    r.y = fmaxf(acc.y * dn + bb.y, 0.f);
    r.z = fmaxf(acc.z * dn + bb.z, 0.f);
    r.w = fmaxf(acc.w * dn + bb.w, 0.f);
    if (SCALE_OUT) { r.x *= dn; r.y *= dn; r.z *= dn; r.w *= dn; }
    reinterpret_cast<float4*>(hout)[w * 32 + lane] = r;
}

// ---------------- sort-pool + conv1d + MLP ----------------
__device__ __forceinline__ int lbound(const int* __restrict__ a, int n, int key) {
    int lo = 0, hi = n;
    while (lo < hi) { int mid = (lo + hi) >> 1; if (a[mid] < key) lo = mid + 1; else hi = mid; }
    return lo;
}

__global__ __launch_bounds__(256) void k_head(const int* __restrict__ batch,
                                              const float* __restrict__ h,
                                              const float* __restrict__ cw,
                                              const float* __restrict__ cb,
                                              const float* __restrict__ l1w,
                                              const float* __restrict__ l1b,
                                              const float* __restrict__ l2w,
                                              const float* __restrict__ l2b,
                                              float* __restrict__ out) {
    const int b = blockIdx.x, tid = threadIdx.x;
    const int lane = tid & 31, wid = tid >> 5;
    const int start = lbound(batch, NN, b);
    const int end   = lbound(batch, NN, b + 1);
    int cnt = end - start;
    if (cnt > 1024) cnt = 1024;

    __shared__ unsigned long long skeys[1024];
    __shared__ unsigned long long wred[8];
    __shared__ int sel[KSEL];
    __shared__ float pooled[KSEL * PSTR];
    __shared__ float flat[COUT * LOUT];
    __shared__ float zz[HD];

    for (int i = tid; i < cnt; i += 256) {
        float v = h[(start + i) * HD + (HD - 1)];
        unsigned u = __float_as_uint(v);
        if (v == 0.0f) u = 0u;
        skeys[i] = ((unsigned long long)u << 32) |
                   (unsigned long long)(0xFFFFFFFFu - (unsigned)i);
    }
    for (int i = tid; i < KSEL * PSTR; i += 256) pooled[i] = 0.f;
    __syncthreads();

    const int m = (cnt < KSEL) ? cnt : KSEL;
    for (int r = 0; r < m; r++) {
        unsigned long long best = 0ULL;
        for (int i = tid; i < cnt; i += 256) {
            unsigned long long k = skeys[i];
            if (k > best) best = k;
        }
        #pragma unroll
        for (int off = 16; off > 0; off >>= 1) {
            unsigned long long o = __shfl_xor_sync(0xFFFFFFFFu, best, off);
            if (o > best) best = o;
        }
        if (lane == 0) wred[wid] = best;
        __syncthreads();
        if (tid == 0) {
            unsigned long long bk = 0ULL;
            #pragma unroll
            for (int qx = 0; qx < 8; qx++) if (wred[qx] > bk) bk = wred[qx];
            int i = (int)(0xFFFFFFFFu - (unsigned)(bk & 0xFFFFFFFFull));
            sel[r] = start + i;
            skeys[i] = 0ULL;
        }
        __syncthreads();
    }

    for (int idx = tid; idx < m * HD; idx += 256) {
        int r = idx >> 7, c = idx & 127;
        pooled[r * PSTR + c] = h[sel[r] * HD + c];
    }
    __syncthreads();

    for (int ot = tid; ot < COUT * LOUT; ot += 256) {
        int o = ot / LOUT, t = ot % LOUT;
        float s = __ldg(&cb[o]);
        const float* wo = cw + o * HD * KERW;
        for (int c = 0; c < HD; c++) {
            float w0 = __ldg(&wo[c * KERW + 0]);
            float w1 = __ldg(&wo[c * KERW + 1]);
            float w2 = __ldg(&wo[c * KERW + 2]);
            float w3 = __ldg(&wo[c * KERW + 3]);
            float w4 = __ldg(&wo[c * KERW + 4]);
            s += pooled[(t + 0) * PSTR + c] * w0;
            s += pooled[(t + 1) * PSTR + c] * w1;
            s += pooled[(t + 2) * PSTR + c] * w2;
            s += pooled[(t + 3) * PSTR + c] * w3;
            s += pooled[(t + 4) * PSTR + c] * w4;
        }
        flat[ot] = fmaxf(s, 0.f);
    }
    __syncthreads();

    if (tid < HD) {
        float s = __ldg(&l1b[tid]);
        #pragma unroll 8
        for (int i = 0; i < COUT * LOUT; i++)
            s += flat[i] * __ldg(&l1w[i * HD + tid]);
        zz[tid] = fmaxf(s, 0.f);
    }
    __syncthreads();

    if (tid < ODIM) {
        float s = __ldg(&l2b[tid]);
        #pragma unroll 8
        for (int i = 0; i < HD; i++)
            s += zz[i] * __ldg(&l2w[i * ODIM + tid]);
        out[b * ODIM + tid] = s;
    }
}

// ---------------- launch: chunked agg->gemm pipeline, double-buffered hw ----------
static cudaStream_t g_s2 = nullptr;
static cudaEvent_t  g_e0 = nullptr, g_e1 = nullptr;
static cudaEvent_t  g_evA1[NCHUNK], g_evA2[NCHUNK];
static cudaEvent_t  g_evG2 = nullptr, g_evG3 = nullptr;

extern "C" void kernel_launch(void* const* d_in, const int* in_sizes, int n_in,
                              void* d_out, int out_size) {
    const float* x     = (const float*)d_in[0];
    const int*   ei    = (const int*)  d_in[1];
    const int*   batch = (const int*)  d_in[2];
    const float* W0 = (const float*)d_in[3];  const float* b0 = (const float*)d_in[4];
    const float* W1 = (const float*)d_in[5];  const float* b1 = (const float*)d_in[6];
    const float* W2 = (const float*)d_in[7];  const float* b2 = (const float*)d_in[8];
    const float* cw = (const float*)d_in[9];  const float* cb = (const float*)d_in[10];
    const float* l1w = (const float*)d_in[11]; const float* l1b = (const float*)d_in[12];
    const float* l2w = (const float*)d_in[13]; const float* l2b = (const float*)d_in[14];
    float* out = (float*)d_out;

    if (g_s2 == nullptr) {
        cudaStreamCreateWithFlags(&g_s2, cudaStreamNonBlocking);
        cudaEventCreateWithFlags(&g_e0, cudaEventDisableTiming);
        cudaEventCreateWithFlags(&g_e1, cudaEventDisableTiming);
        for (int c = 0; c < NCHUNK; c++) {
            cudaEventCreateWithFlags(&g_evA1[c], cudaEventDisableTiming);
            cudaEventCreateWithFlags(&g_evA2[c], cudaEventDisableTiming);
        }
        cudaEventCreateWithFlags(&g_evG2, cudaEventDisableTiming);
        cudaEventCreateWithFlags(&g_evG3, cudaEventDisableTiming);
    }
    const bool fork = (g_s2 != nullptr && g_e0 != nullptr && g_e1 != nullptr &&
                       g_evG2 != nullptr && g_evG3 != nullptr);

    void *p1 = nullptr, *p2 = nullptr, *pA = nullptr, *pB = nullptr;
    cudaGetSymbolAddress(&p1, g_hw1);
    cudaGetSymbolAddress(&p2, g_hw2);
    cudaGetSymbolAddress(&pA, g_hA);
    cudaGetSymbolAddress(&pB, g_hB);
    float* hw1 = (float*)p1;
    float* hw2 = (float*)p2;
    float* hA  = (float*)pA;
    float* hB  = (float*)pB;

    const int gemm_blocks_full = (NN + 127) / 128;   // 391
    const int agg_blocks_full  = (NN + 7) / 8;       // 6250

    if (!fork) {
        k_init<<<(NN + 255) / 256, 256>>>();
        k_fill<<<(TE + 255) / 256, 256>>>(ei);
        k_dinv<<<(NN + 255) / 256, 256>>>();
        k_gemm<<<gemm_blocks_full, 256>>>(x, W0, hw1, 0);
        k_agg<true, true><<<agg_blocks_full, 256>>>(hw1, b0, hA, 0, NN);
        k_gemm<<<gemm_blocks_full, 256>>>(hA, W1, hw2, 0);
        k_agg<false, true><<<agg_blocks_full, 256>>>(hw2, b1, hB, 0, NN);
        k_gemm<<<gemm_blocks_full, 256>>>(hB, W2, hw1, 0);
        k_agg<false, false><<<agg_blocks_full, 256>>>(hw1, b2, hA, 0, NN);
        k_head<<<BB, 256>>>(batch, hA, cw, cb, l1w, l1b, l2w, l2b, out);
        return;
    }

    cudaStream_t s0 = (cudaStream_t)0;
    cudaStream_t s1 = g_s2;

    // ---- CSR build on s1, overlapping gemm1 on s0 ----
    cudaEventRecord(g_e0, s0);
    cudaStreamWaitEvent(s1, g_e0, 0);
    k_init<<<(NN + 255) / 256, 256, 0, s1>>>();
    k_fill<<<(TE + 255) / 256, 256, 0, s1>>>(ei);
    k_dinv<<<(NN + 255) / 256, 256, 0, s1>>>();
    cudaEventRecord(g_e1, s1);

    // ---- layer 1 GEMM (full) -> hw1 on s0 ----
    k_gemm<<<gemm_blocks_full, 256, 0, s0>>>(x, W0, hw1, 0);
    cudaStreamWaitEvent(s0, g_e1, 0);

    // ---- agg1 (reads hw1) chunks on s0; gemm2 (writes hw2) chunks on s1 ----
    for (int c = 0; c < NCHUNK; c++) {
        int n0 = CH_START[c], n1 = CH_START[c + 1];
        k_agg<true, true><<<((n1 - n0) + 7) / 8, 256, 0, s0>>>(hw1, b0, hA, n0, n1);
        cudaEventRecord(g_evA1[c], s0);
        cudaStreamWaitEvent(s1, g_evA1[c], 0);
        k_gemm<<<((n1 - n0) + 127) / 128, 256, 0, s1>>>(hA, W1, hw2, n0);
    }
    cudaEventRecord(g_evG2, s1);
    cudaStreamWaitEvent(s0, g_evG2, 0);

    // ---- agg2 (reads hw2) chunks on s0; gemm3 (writes hw1) chunks on s1 ----
    for (int c = 0; c < NCHUNK; c++) {
        int n0 = CH_START[c], n1 = CH_START[c + 1];
        k_agg<false, true><<<((n1 - n0) + 7) / 8, 256, 0, s0>>>(hw2, b1, hB, n0, n1);
        cudaEventRecord(g_evA2[c], s0);
        cudaStreamWaitEvent(s1, g_evA2[c], 0);
        k_gemm<<<((n1 - n0) + 127) / 128, 256, 0, s1>>>(hB, W2, hw1, n0);
    }
    cudaEventRecord(g_evG3, s1);
    cudaStreamWaitEvent(s0, g_evG3, 0);

    // ---- agg3 (reads hw1, full) + head on s0 ----
    k_agg<false, false><<<agg_blocks_full, 256, 0, s0>>>(hw1, b2, hA, 0, NN);
    k_head<<<BB, 256, 0, s0>>>(batch, hA, cw, cb, l1w, l1b, l2w, l2b, out);
}

// round 13
// speedup vs baseline: 1.1252x; 1.1252x over previous
#include <cuda_runtime.h>
#include <cstdint>

#define NN    50000
#define NE    600000
#define TE    (NE + NN)
#define HD    128
#define BB    128
#define KSEL  30
#define COUT  32
#define KERW  5
#define LOUT  26
#define ODIM  10
#define PSTR  129
#define DSLOT 64      // fixed per-node edge slots (Poisson(13) -> max deg << 64)

// ---- tf32 GEMM smem layout (floats) ----
#define ASTR 36
#define BSTR 136
#define SM_AH 0
#define SM_AL (128 * ASTR)
#define SM_BH (2 * 128 * ASTR)
#define SM_BL (2 * 128 * ASTR + 32 * BSTR)
#define GSM_FLOATS (2 * 128 * ASTR + 2 * 32 * BSTR)
#define GSM_BYTES (GSM_FLOATS * 4)      // 71,680 B

// ---------------- device scratch ----------------
static __device__ int   g_cur[NN];
static __device__ float g_dinv[NN];
static __device__ __align__(16) int g_srcv[NN * DSLOT];
static __device__ float g_hw[NN * HD];
static __device__ float g_hA[NN * HD];
static __device__ float g_hB[NN * HD];

// ---------------- graph build (bucketed, no scan) ----------------
__global__ void k_init() {
    int i = blockIdx.x * 256 + threadIdx.x;
    if (i < NN) g_cur[i] = 0;
}

__global__ void k_fill(const int* __restrict__ ei) {
    int e = blockIdx.x * 256 + threadIdx.x;
    if (e >= TE) return;
    int src, dst;
    if (e < NE) { src = ei[e]; dst = ei[NE + e]; }
    else        { src = dst = e - NE; }          // self-loop
    int pos = atomicAdd(&g_cur[dst], 1);
    if (pos < DSLOT) g_srcv[dst * DSLOT + pos] = src;
}

__global__ void k_dinv() {
    int i = blockIdx.x * 256 + threadIdx.x;
    if (i < NN) g_dinv[i] = rsqrtf((float)g_cur[i]);
}

// ---------------- TF32 split GEMM: g_hw = A(NNxHD) @ W(HDxHD) ----------------
// D = Ah@Wh + Ah@Wl + Al@Wh (tf32 hi/lo split; dropped lo*lo ~ 2^-22 rel).
// Block 128x128, 8 warps, warp tile 64x32 (4x4 m16n8k8 tiles), K-step 8.
__device__ __forceinline__ uint32_t f2tf(float x) {
    uint32_t r;
    asm("cvt.rna.tf32.f32 %0, %1;" : "=r"(r) : "f"(x));
    return r;
}
__device__ __forceinline__ void mma8(float* c, const uint32_t* a, const uint32_t* b) {
    asm volatile("mma.sync.aligned.m16n8k8.row.col.f32.tf32.tf32.f32 "
                 "{%0,%1,%2,%3}, {%4,%5,%6,%7}, {%8,%9}, {%0,%1,%2,%3};"
                 : "+f"(c[0]), "+f"(c[1]), "+f"(c[2]), "+f"(c[3])
                 : "r"(a[0]), "r"(a[1]), "r"(a[2]), "r"(a[3]), "r"(b[0]), "r"(b[1]));
}

__global__ __launch_bounds__(256, 2) void k_gemm(const float* __restrict__ A,
                                                 const float* __restrict__ W) {
    extern __shared__ float sm[];
    float* Ah = sm + SM_AH;
    float* Al = sm + SM_AL;
    float* Bh = sm + SM_BH;
    float* Bl = sm + SM_BL;
    const int tid = threadIdx.x;
    const int lane = tid & 31, wid = tid >> 5;
    const int wm = wid >> 2, wn = wid & 3;       // warp tile origin: (wm*64, wn*32)
    const int m0 = blockIdx.x * 128;
    const int gid = lane >> 2, qid = lane & 3;   // groupID / tid-in-group

    float acc[4][4][4];
    #pragma unroll
    for (int mt = 0; mt < 4; mt++)
        #pragma unroll
        for (int nt = 0; nt < 4; nt++)
            #pragma unroll
            for (int u = 0; u < 4; u++) acc[mt][nt][u] = 0.f;

    for (int kb = 0; kb < 4; kb++) {
        const int k0 = kb * 32;
        // ---- load + split A tile (128 x 32) ----
        #pragma unroll
        for (int it = 0; it < 4; it++) {
            int idx = it * 256 + tid;
            int r = idx >> 3, q = (idx & 7) * 4;
            int grow = m0 + r;
            float4 v = make_float4(0.f, 0.f, 0.f, 0.f);
            if (grow < NN) v = *reinterpret_cast<const float4*>(&A[grow * HD + k0 + q]);
            float vv[4] = {v.x, v.y, v.z, v.w};
            #pragma unroll
            for (int j = 0; j < 4; j++) {
                uint32_t h = f2tf(vv[j]);
                float hf = __uint_as_float(h);
                uint32_t l = f2tf(vv[j] - hf);
                Ah[r * ASTR + q + j] = hf;
                Al[r * ASTR + q + j] = __uint_as_float(l);
            }
        }
        // ---- load + split W tile (32 x 128) ----
        #pragma unroll
        for (int it = 0; it < 4; it++) {
            int idx = it * 256 + tid;
            int k = idx >> 5, n4 = (idx & 31) * 4;
            float4 v = *reinterpret_cast<const float4*>(&W[(k0 + k) * HD + n4]);
            float vv[4] = {v.x, v.y, v.z, v.w};
            #pragma unroll
            for (int j = 0; j < 4; j++) {
                uint32_t h = f2tf(vv[j]);
                float hf = __uint_as_float(h);
                uint32_t l = f2tf(vv[j] - hf);
                Bh[k * BSTR + n4 + j] = hf;
                Bl[k * BSTR + n4 + j] = __uint_as_float(l);
            }
        }
        __syncthreads();

        #pragma unroll
        for (int ks = 0; ks < 4; ks++) {
            const int kk = ks * 8;
            uint32_t af[4][4], bh[4][2], bl[4][2];
            // A_hi fragments
            #pragma unroll
            for (int mt = 0; mt < 4; mt++) {
                int rb = wm * 64 + mt * 16 + gid;
                int c = kk + qid;
                af[mt][0] = __float_as_uint(Ah[rb * ASTR + c]);
                af[mt][1] = __float_as_uint(Ah[(rb + 8) * ASTR + c]);
                af[mt][2] = __float_as_uint(Ah[rb * ASTR + c + 4]);
                af[mt][3] = __float_as_uint(Ah[(rb + 8) * ASTR + c + 4]);
            }
            // B_hi / B_lo fragments
            #pragma unroll
            for (int nt = 0; nt < 4; nt++) {
                int kr = kk + qid;
                int cn = wn * 32 + nt * 8 + gid;
                bh[nt][0] = __float_as_uint(Bh[kr * BSTR + cn]);
                bh[nt][1] = __float_as_uint(Bh[(kr + 4) * BSTR + cn]);
                bl[nt][0] = __float_as_uint(Bl[kr * BSTR + cn]);
                bl[nt][1] = __float_as_uint(Bl[(kr + 4) * BSTR + cn]);
            }
            // hh + hl
            #pragma unroll
            for (int mt = 0; mt < 4; mt++)
                #pragma unroll
                for (int nt = 0; nt < 4; nt++) {
                    mma8(acc[mt][nt], af[mt], bh[nt]);
                    mma8(acc[mt][nt], af[mt], bl[nt]);
                }
            // reload af <- A_lo, then lh
            #pragma unroll
            for (int mt = 0; mt < 4; mt++) {
                int rb = wm * 64 + mt * 16 + gid;
                int c = kk + qid;
                af[mt][0] = __float_as_uint(Al[rb * ASTR + c]);
                af[mt][1] = __float_as_uint(Al[(rb + 8) * ASTR + c]);
                af[mt][2] = __float_as_uint(Al[rb * ASTR + c + 4]);
                af[mt][3] = __float_as_uint(Al[(rb + 8) * ASTR + c + 4]);
            }
            #pragma unroll
            for (int mt = 0; mt < 4; mt++)
                #pragma unroll
                for (int nt = 0; nt < 4; nt++)
                    mma8(acc[mt][nt], af[mt], bh[nt]);
        }
        __syncthreads();
    }

    // ---- epilogue ----
    #pragma unroll
    for (int mt = 0; mt < 4; mt++) {
        int row = m0 + wm * 64 + mt * 16 + gid;
        #pragma unroll
        for (int nt = 0; nt < 4; nt++) {
            int col = wn * 32 + nt * 8 + qid * 2;
            if (row < NN) {
                float2 p0 = make_float2(acc[mt][nt][0], acc[mt][nt][1]);
                *reinterpret_cast<float2*>(&g_hw[row * HD + col]) = p0;
            }
            if (row + 8 < NN) {
                float2 p1 = make_float2(acc[mt][nt][2], acc[mt][nt][3]);
                *reinterpret_cast<float2*>(&g_hw[(row + 8) * HD + col]) = p1;
            }
        }
    }
}

// ---------------- aggregation: warp per node (round-7 proven) ----------------
// GATHER_DINV: per-edge dinv scaling (layer 1 only).
// SCALE_OUT:   multiply relu output by dinv[w] (pre-scales rows for next layer).
template<bool GATHER_DINV, bool SCALE_OUT>
__global__ __launch_bounds__(256) void k_agg(const float* __restrict__ bias,
                                             float* __restrict__ hout) {
    int w = (blockIdx.x * 256 + threadIdx.x) >> 5;
    int lane = threadIdx.x & 31;
    if (w >= NN) return;
    int deg = g_cur[w]; if (deg > DSLOT) deg = DSLOT;
    const int* lst = &g_srcv[w * DSLOT];
    const float4* hw4 = reinterpret_cast<const float4*>(g_hw);
    float4 acc = make_float4(0.f, 0.f, 0.f, 0.f);

    int e = 0;
    for (; e + 8 <= deg; e += 8) {
        int s[8];
        #pragma unroll
        for (int u = 0; u < 8; u++) s[u] = __ldg(&lst[e + u]);
        float c[8];
        #pragma unroll
        for (int u = 0; u < 8; u++) c[u] = GATHER_DINV ? __ldg(&g_dinv[s[u]]) : 1.f;
        float4 v[8];
        #pragma unroll
        for (int u = 0; u < 8; u++) v[u] = __ldg(&hw4[s[u] * 32 + lane]);
        #pragma unroll
        for (int u = 0; u < 8; u++) {
            if (GATHER_DINV) {
                acc.x += c[u] * v[u].x; acc.y += c[u] * v[u].y;
                acc.z += c[u] * v[u].z; acc.w += c[u] * v[u].w;
            } else {
                acc.x += v[u].x; acc.y += v[u].y;
                acc.z += v[u].z; acc.w += v[u].w;
            }
        }
    }
    if (e + 4 <= deg) {
        int s[4];
        #pragma unroll
        for (int u = 0; u < 4; u++) s[u] = __ldg(&lst[e + u]);
        float c[4];
        #pragma unroll
        for (int u = 0; u < 4; u++) c[u] = GATHER_DINV ? __ldg(&g_dinv[s[u]]) : 1.f;
        float4 v[4];
        #pragma unroll
        for (int u = 0; u < 4; u++) v[u] = __ldg(&hw4[s[u] * 32 + lane]);
        #pragma unroll
        for (int u = 0; u < 4; u++) {
            if (GATHER_DINV) {
                acc.x += c[u] * v[u].x; acc.y += c[u] * v[u].y;
                acc.z += c[u] * v[u].z; acc.w += c[u] * v[u].w;
            } else {
                acc.x += v[u].x; acc.y += v[u].y;
                acc.z += v[u].z; acc.w += v[u].w;
            }
        }
        e += 4;
    }
    for (; e < deg; e++) {
        int s = __ldg(&lst[e]);
        float c = GATHER_DINV ? __ldg(&g_dinv[s]) : 1.f;
        float4 v = __ldg(&hw4[s * 32 + lane]);
        if (GATHER_DINV) {
            acc.x += c * v.x; acc.y += c * v.y; acc.z += c * v.z; acc.w += c * v.w;
        } else {
            acc.x += v.x; acc.y += v.y; acc.z += v.z; acc.w += v.w;
        }
    }

    float dn = g_dinv[w];
    float4 bb = reinterpret_cast<const float4*>(bias)[lane];
    float4 r;
    r.x = fmaxf(acc.x * dn + bb.x, 0.f);
    r.y = fmaxf(acc.y * dn + bb.y, 0.f);
    r.z = fmaxf(acc.z * dn + bb.z, 0.f);
    r.w = fmaxf(acc.w * dn + bb.w, 0.f);
    if (SCALE_OUT) { r.x *= dn; r.y *= dn; r.z *= dn; r.w *= dn; }
    reinterpret_cast<float4*>(hout)[w * 32 + lane] = r;
}

// ---------------- sort-pool + conv1d + MLP ----------------
__device__ __forceinline__ int lbound(const int* __restrict__ a, int n, int key) {
    int lo = 0, hi = n;
    while (lo < hi) { int mid = (lo + hi) >> 1; if (a[mid] < key) lo = mid + 1; else hi = mid; }
    return lo;
}

__global__ __launch_bounds__(256) void k_head(const int* __restrict__ batch,
                                              const float* __restrict__ h,
                                              const float* __restrict__ cw,
                                              const float* __restrict__ cb,
                                              const float* __restrict__ l1w,
                                              const float* __restrict__ l1b,
                                              const float* __restrict__ l2w,
                                              const float* __restrict__ l2b,
                                              float* __restrict__ out) {
    const int b = blockIdx.x, tid = threadIdx.x;
    const int lane = tid & 31, wid = tid >> 5;
    const int start = lbound(batch, NN, b);
    const int end   = lbound(batch, NN, b + 1);
    int cnt = end - start;
    if (cnt > 1024) cnt = 1024;

    __shared__ unsigned long long skeys[1024];
    __shared__ unsigned long long wred[8];
    __shared__ int sel[KSEL];
    __shared__ float pooled[KSEL * PSTR];
    __shared__ float flat[COUT * LOUT];
    __shared__ float zz[HD];

    for (int i = tid; i < cnt; i += 256) {
        float v = h[(start + i) * HD + (HD - 1)];
        unsigned u = __float_as_uint(v);
        if (v == 0.0f) u = 0u;
        skeys[i] = ((unsigned long long)u << 32) |
                   (unsigned long long)(0xFFFFFFFFu - (unsigned)i);
    }
    for (int i = tid; i < KSEL * PSTR; i += 256) pooled[i] = 0.f;
    __syncthreads();

    const int m = (cnt < KSEL) ? cnt : KSEL;
    for (int r = 0; r < m; r++) {
        unsigned long long best = 0ULL;
        for (int i = tid; i < cnt; i += 256) {
            unsigned long long k = skeys[i];
            if (k > best) best = k;
        }
        #pragma unroll
        for (int off = 16; off > 0; off >>= 1) {
            unsigned long long o = __shfl_xor_sync(0xFFFFFFFFu, best, off);
            if (o > best) best = o;
        }
        if (lane == 0) wred[wid] = best;
        __syncthreads();
        if (tid == 0) {
            unsigned long long bk = 0ULL;
            #pragma unroll
            for (int qx = 0; qx < 8; qx++) if (wred[qx] > bk) bk = wred[qx];
            int i = (int)(0xFFFFFFFFu - (unsigned)(bk & 0xFFFFFFFFull));
            sel[r] = start + i;
            skeys[i] = 0ULL;
        }
        __syncthreads();
    }

    for (int idx = tid; idx < m * HD; idx += 256) {
        int r = idx >> 7, c = idx & 127;
        pooled[r * PSTR + c] = h[sel[r] * HD + c];
    }
    __syncthreads();

    for (int ot = tid; ot < COUT * LOUT; ot += 256) {
        int o = ot / LOUT, t = ot % LOUT;
        float s = __ldg(&cb[o]);
        const float* wo = cw + o * HD * KERW;
        for (int c = 0; c < HD; c++) {
            float w0 = __ldg(&wo[c * KERW + 0]);
            float w1 = __ldg(&wo[c * KERW + 1]);
            float w2 = __ldg(&wo[c * KERW + 2]);
            float w3 = __ldg(&wo[c * KERW + 3]);
            float w4 = __ldg(&wo[c * KERW + 4]);
            s += pooled[(t + 0) * PSTR + c] * w0;
            s += pooled[(t + 1) * PSTR + c] * w1;
            s += pooled[(t + 2) * PSTR + c] * w2;
            s += pooled[(t + 3) * PSTR + c] * w3;
            s += pooled[(t + 4) * PSTR + c] * w4;
        }
        flat[ot] = fmaxf(s, 0.f);
    }
    __syncthreads();

    if (tid < HD) {
        float s = __ldg(&l1b[tid]);
        #pragma unroll 8
        for (int i = 0; i < COUT * LOUT; i++)
            s += flat[i] * __ldg(&l1w[i * HD + tid]);
        zz[tid] = fmaxf(s, 0.f);
    }
    __syncthreads();

    if (tid < ODIM) {
        float s = __ldg(&l2b[tid]);
        #pragma unroll 8
        for (int i = 0; i < HD; i++)
            s += zz[i] * __ldg(&l2w[i * ODIM + tid]);
        out[b * ODIM + tid] = s;
    }
}

// ---------------- launch (round-7 structure: CSR fork only) ----------------
static cudaStream_t g_s2 = nullptr;
static cudaEvent_t  g_e0 = nullptr, g_e1 = nullptr;

extern "C" void kernel_launch(void* const* d_in, const int* in_sizes, int n_in,
                              void* d_out, int out_size) {
    const float* x     = (const float*)d_in[0];
    const int*   ei    = (const int*)  d_in[1];
    const int*   batch = (const int*)  d_in[2];
    const float* W0 = (const float*)d_in[3];  const float* b0 = (const float*)d_in[4];
    const float* W1 = (const float*)d_in[5];  const float* b1 = (const float*)d_in[6];
    const float* W2 = (const float*)d_in[7];  const float* b2 = (const float*)d_in[8];
    const float* cw = (const float*)d_in[9];  const float* cb = (const float*)d_in[10];
    const float* l1w = (const float*)d_in[11]; const float* l1b = (const float*)d_in[12];
    const float* l2w = (const float*)d_in[13]; const float* l2b = (const float*)d_in[14];
    float* out = (float*)d_out;

    if (g_s2 == nullptr) {
        cudaStreamCreateWithFlags(&g_s2, cudaStreamNonBlocking);
        cudaEventCreateWithFlags(&g_e0, cudaEventDisableTiming);
        cudaEventCreateWithFlags(&g_e1, cudaEventDisableTiming);
        cudaFuncSetAttribute(k_gemm, cudaFuncAttributeMaxDynamicSharedMemorySize, GSM_BYTES);
    }
    const bool fork = (g_s2 != nullptr && g_e0 != nullptr && g_e1 != nullptr);
    cudaStream_t cs = fork ? g_s2 : (cudaStream_t)0;

    void *pA = nullptr, *pB = nullptr;
    cudaGetSymbolAddress(&pA, g_hA);
    cudaGetSymbolAddress(&pB, g_hB);
    float* hA = (float*)pA;
    float* hB = (float*)pB;

    if (fork) {
        cudaEventRecord(g_e0, 0);
        cudaStreamWaitEvent(cs, g_e0, 0);
    }
    k_init<<<(NN + 255) / 256, 256, 0, cs>>>();
    k_fill<<<(TE + 255) / 256, 256, 0, cs>>>(ei);
    k_dinv<<<(NN + 255) / 256, 256, 0, cs>>>();
    if (fork) cudaEventRecord(g_e1, cs);

    const int gemm_blocks = (NN + 127) / 128;   // 391
    const int agg_blocks  = (NN + 7) / 8;       // 6250

    // layer 1: GEMM overlaps CSR build; agg gathers per-edge dinv, writes pre-scaled rows
    k_gemm<<<gemm_blocks, 256, GSM_BYTES>>>(x, W0);
    if (fork) cudaStreamWaitEvent(0, g_e1, 0);
    k_agg<true, true><<<agg_blocks, 256>>>(b0, hA);

    // layer 2: rows pre-scaled -> pure row-sum gather; output pre-scaled again
    k_gemm<<<gemm_blocks, 256, GSM_BYTES>>>(hA, W1);
    k_agg<false, true><<<agg_blocks, 256>>>(b1, hB);

    // layer 3: rows pre-scaled; output UNscaled (feeds head)
    k_gemm<<<gemm_blocks, 256, GSM_BYTES>>>(hB, W2);
    k_agg<false, false><<<agg_blocks, 256>>>(b2, hA);

    k_head<<<BB, 256>>>(batch, hA, cw, cb, l1w, l1b, l2w, l2b, out);
}